// round 8
// baseline (speedup 1.0000x reference)
#include <cuda_runtime.h>
#include <cuda_bf16.h>

// Fixed problem shape.
#define BB 4
#define CC 512
#define TT 1024
#define HH 8
#define DD 64
#define NREL 9
#define QPAD 68    // padded row stride (floats); 272B, 16B-aligned
#define KPAD 132   // Kt row stride (128 n + 4 pad)
#define VPAD 68    // Vs row stride

// Scratch (no allocations allowed) — 32 MB total.
__device__ float g_Q[BB*HH*TT*DD];   // [B,H,T,d]
__device__ float g_K[BB*HH*TT*DD];   // [B,H,T,d]
__device__ float g_V[BB*HH*TT*DD];   // [B,H,T,d]
__device__ float g_O[BB*CC*TT];      // [B,C,T] attention output (pre-Wo)

// ---- packed f32x2 helpers (sm_100+: SASS FFMA2; only reachable via PTX) ----
typedef unsigned long long u64t;

__device__ __forceinline__ u64t pk2(float lo, float hi) {
    u64t d;
    asm("mov.b64 %0, {%1, %2};"
        : "=l"(d) : "r"(__float_as_uint(lo)), "r"(__float_as_uint(hi)));
    return d;
}
__device__ __forceinline__ void upk2(u64t v, float& lo, float& hi) {
    unsigned a, b;
    asm("mov.b64 {%0, %1}, %2;" : "=r"(a), "=r"(b) : "l"(v));
    lo = __uint_as_float(a); hi = __uint_as_float(b);
}
__device__ __forceinline__ void fma2(u64t& d, u64t a, u64t b) {
    asm("fma.rn.f32x2 %0, %1, %2, %0;" : "+l"(d) : "l"(a), "l"(b));
}
__device__ __forceinline__ void mul2(u64t& d, u64t a) {
    asm("mul.rn.f32x2 %0, %0, %1;" : "+l"(d) : "l"(a));
}

// ---------------------------------------------------------------------------
// Fused QKV projection, double-buffered, FFMA2 micro-kernel (proven: 145us).
// ---------------------------------------------------------------------------
__global__ __launch_bounds__(256)
void qkv_kernel(const float* __restrict__ Wq, const float* __restrict__ bq_,
                const float* __restrict__ Wk, const float* __restrict__ bk_,
                const float* __restrict__ Wv, const float* __restrict__ bv_,
                const float* __restrict__ X)
{
    __shared__ float Ws[2][3][16][64];   // [buf][g][kk][m]
    __shared__ float Xs[2][16][64];      // [buf][kk][n]

    const int b  = blockIdx.z;
    const int h  = blockIdx.y;
    const int o0 = h * 64;
    const int t0 = blockIdx.x * 64;
    const int tid = threadIdx.x;
    const int ty = tid >> 4, tx = tid & 15;
    const int m0 = ty * 4, n0 = tx * 4;
    const int wm  = tid >> 2;
    const int wk4 = (tid & 3) * 4;
    const int xkk = tid >> 4;
    const int xnn = (tid & 15) * 4;

    const float* Xb = X + (size_t)b * CC * TT;

    u64t acc2[3][2][4] = {};

    float4 wr0 = *reinterpret_cast<const float4*>(&Wq[(size_t)(o0 + wm) * CC + wk4]);
    float4 wr1 = *reinterpret_cast<const float4*>(&Wk[(size_t)(o0 + wm) * CC + wk4]);
    float4 wr2 = *reinterpret_cast<const float4*>(&Wv[(size_t)(o0 + wm) * CC + wk4]);
    float4 xr  = *reinterpret_cast<const float4*>(&Xb[(size_t)xkk * TT + t0 + xnn]);
    Ws[0][0][wk4+0][wm] = wr0.x; Ws[0][0][wk4+1][wm] = wr0.y;
    Ws[0][0][wk4+2][wm] = wr0.z; Ws[0][0][wk4+3][wm] = wr0.w;
    Ws[0][1][wk4+0][wm] = wr1.x; Ws[0][1][wk4+1][wm] = wr1.y;
    Ws[0][1][wk4+2][wm] = wr1.z; Ws[0][1][wk4+3][wm] = wr1.w;
    Ws[0][2][wk4+0][wm] = wr2.x; Ws[0][2][wk4+1][wm] = wr2.y;
    Ws[0][2][wk4+2][wm] = wr2.z; Ws[0][2][wk4+3][wm] = wr2.w;
    *reinterpret_cast<float4*>(&Xs[0][xkk][xnn]) = xr;
    __syncthreads();

    int p = 0;
    for (int it = 0; it < CC / 16; it++) {
        const int c1 = (it + 1) * 16;
        if (it < CC / 16 - 1) {
            wr0 = *reinterpret_cast<const float4*>(&Wq[(size_t)(o0 + wm) * CC + c1 + wk4]);
            wr1 = *reinterpret_cast<const float4*>(&Wk[(size_t)(o0 + wm) * CC + c1 + wk4]);
            wr2 = *reinterpret_cast<const float4*>(&Wv[(size_t)(o0 + wm) * CC + c1 + wk4]);
            xr  = *reinterpret_cast<const float4*>(&Xb[(size_t)(c1 + xkk) * TT + t0 + xnn]);
        }
        #pragma unroll
        for (int kk = 0; kk < 16; kk++) {
            float4 xb = *reinterpret_cast<float4*>(&Xs[p][kk][n0]);
            u64t bd[4];
            bd[0] = pk2(xb.x, xb.x); bd[1] = pk2(xb.y, xb.y);
            bd[2] = pk2(xb.z, xb.z); bd[3] = pk2(xb.w, xb.w);
            #pragma unroll
            for (int g = 0; g < 3; g++) {
                float4 wa = *reinterpret_cast<float4*>(&Ws[p][g][kk][m0]);
                u64t a01 = pk2(wa.x, wa.y);
                u64t a23 = pk2(wa.z, wa.w);
                #pragma unroll
                for (int j = 0; j < 4; j++) {
                    fma2(acc2[g][0][j], a01, bd[j]);
                    fma2(acc2[g][1][j], a23, bd[j]);
                }
            }
        }
        if (it < CC / 16 - 1) {
            const int np = p ^ 1;
            Ws[np][0][wk4+0][wm] = wr0.x; Ws[np][0][wk4+1][wm] = wr0.y;
            Ws[np][0][wk4+2][wm] = wr0.z; Ws[np][0][wk4+3][wm] = wr0.w;
            Ws[np][1][wk4+0][wm] = wr1.x; Ws[np][1][wk4+1][wm] = wr1.y;
            Ws[np][1][wk4+2][wm] = wr1.z; Ws[np][1][wk4+3][wm] = wr1.w;
            Ws[np][2][wk4+0][wm] = wr2.x; Ws[np][2][wk4+1][wm] = wr2.y;
            Ws[np][2][wk4+2][wm] = wr2.z; Ws[np][2][wk4+3][wm] = wr2.w;
            *reinterpret_cast<float4*>(&Xs[np][xkk][xnn]) = xr;
        }
        __syncthreads();
        p ^= 1;
    }

    #pragma unroll
    for (int g = 0; g < 3; g++) {
        const float* bias = (g == 0) ? bq_ : (g == 1) ? bk_ : bv_;
        float bb0 = bias[o0 + m0 + 0];
        float bb1 = bias[o0 + m0 + 1];
        float bb2 = bias[o0 + m0 + 2];
        float bb3 = bias[o0 + m0 + 3];
        float* Yb = ((g == 0) ? g_Q : (g == 1) ? g_K : g_V)
                    + (((size_t)b * HH + h) * TT + t0) * DD;
        #pragma unroll
        for (int j = 0; j < 4; j++) {
            float f0, f1, f2, f3;
            upk2(acc2[g][0][j], f0, f1);
            upk2(acc2[g][1][j], f2, f3);
            float4 v;
            v.x = f0 + bb0; v.y = f1 + bb1; v.z = f2 + bb2; v.w = f3 + bb3;
            *reinterpret_cast<float4*>(&Yb[(size_t)(n0 + j) * DD + m0]) = v;
        }
    }
}

// ---------------------------------------------------------------------------
// Output projection (proven), double-buffered FFMA2.
// ---------------------------------------------------------------------------
__global__ __launch_bounds__(256)
void out_kernel(const float* __restrict__ W, const float* __restrict__ bias,
                const float* __restrict__ X, float* __restrict__ Y)
{
    __shared__ float Ws[2][16][64];
    __shared__ float Xs[2][16][64];

    const int b  = blockIdx.z;
    const int o0 = blockIdx.y * 64;
    const int t0 = blockIdx.x * 64;
    const int tid = threadIdx.x;
    const int ty = tid >> 4, tx = tid & 15;
    const int m0 = ty * 4, n0 = tx * 4;
    const int wm  = tid >> 2;
    const int wk4 = (tid & 3) * 4;
    const int xkk = tid >> 4;
    const int xnn = (tid & 15) * 4;

    const float* Xb = X + (size_t)b * CC * TT;

    u64t acc2[2][4] = {};

    float4 wr = *reinterpret_cast<const float4*>(&W[(size_t)(o0 + wm) * CC + wk4]);
    float4 xr = *reinterpret_cast<const float4*>(&Xb[(size_t)xkk * TT + t0 + xnn]);
    Ws[0][wk4+0][wm] = wr.x; Ws[0][wk4+1][wm] = wr.y;
    Ws[0][wk4+2][wm] = wr.z; Ws[0][wk4+3][wm] = wr.w;
    *reinterpret_cast<float4*>(&Xs[0][xkk][xnn]) = xr;
    __syncthreads();

    int p = 0;
    for (int it = 0; it < CC / 16; it++) {
        const int c1 = (it + 1) * 16;
        if (it < CC / 16 - 1) {
            wr = *reinterpret_cast<const float4*>(&W[(size_t)(o0 + wm) * CC + c1 + wk4]);
            xr = *reinterpret_cast<const float4*>(&Xb[(size_t)(c1 + xkk) * TT + t0 + xnn]);
        }
        #pragma unroll
        for (int kk = 0; kk < 16; kk++) {
            float4 xb = *reinterpret_cast<float4*>(&Xs[p][kk][n0]);
            float4 wa = *reinterpret_cast<float4*>(&Ws[p][kk][m0]);
            u64t a01 = pk2(wa.x, wa.y);
            u64t a23 = pk2(wa.z, wa.w);
            u64t bd[4];
            bd[0] = pk2(xb.x, xb.x); bd[1] = pk2(xb.y, xb.y);
            bd[2] = pk2(xb.z, xb.z); bd[3] = pk2(xb.w, xb.w);
            #pragma unroll
            for (int j = 0; j < 4; j++) {
                fma2(acc2[0][j], a01, bd[j]);
                fma2(acc2[1][j], a23, bd[j]);
            }
        }
        if (it < CC / 16 - 1) {
            const int np = p ^ 1;
            Ws[np][wk4+0][wm] = wr.x; Ws[np][wk4+1][wm] = wr.y;
            Ws[np][wk4+2][wm] = wr.z; Ws[np][wk4+3][wm] = wr.w;
            *reinterpret_cast<float4*>(&Xs[np][xkk][xnn]) = xr;
        }
        __syncthreads();
        p ^= 1;
    }

    float accv[4][4];
    #pragma unroll
    for (int j = 0; j < 4; j++) {
        upk2(acc2[0][j], accv[0][j], accv[1][j]);
        upk2(acc2[1][j], accv[2][j], accv[3][j]);
    }
    #pragma unroll
    for (int i = 0; i < 4; i++) {
        float bv = bias[o0 + m0 + i];
        float4 v;
        v.x = accv[i][0] + bv; v.y = accv[i][1] + bv;
        v.z = accv[i][2] + bv; v.w = accv[i][3] + bv;
        *reinterpret_cast<float4*>(
            &Y[((size_t)b * CC + o0 + m0 + i) * TT + t0 + n0]) = v;
    }
}

// ---------------------------------------------------------------------------
// Flash attention, 128-wide s-tiles, Kt/Pt smem union, natural-pair FFMA2.
//   score[t,s] = (q.k)/8 + [|s-t|<=4](q.Ek[s-t+4])/8 ; mask==0 -> -10000
//   out[t]     = softmax(score) @ V + sum_e p[t, t+e-4] * Ev[e]
// One block = (b, h, 64-query tile). 256 threads.
// QK micro: 4r x 8n (acc packed over n); PV micro: 4r x 4d (packed over d).
// ---------------------------------------------------------------------------
#define UNION_FLOATS 8704   // max(64*KPAD=8448, 128*QPAD=8704)
#define SMEM_ATTN_FLOATS (64*QPAD + UNION_FLOATS + 128*VPAD \
                          + NREL*QPAD + NREL*QPAD + 64*NREL + 64*NREL \
                          + 64*3 + 128)

__global__ __launch_bounds__(256, 2)
void attn_kernel(const int* __restrict__ mask,
                 const float* __restrict__ Ek, const float* __restrict__ Ev)
{
    extern __shared__ float sm[];
    float* Qt    = sm;                    // [64][QPAD]  Qt[k][r], pre-scaled by 1/8
    float* Kt    = Qt + 64*QPAD;          // union: Kt[64][KPAD]
    float* Pt    = Kt;                    //        Pt[128][QPAD] (aliases Kt)
    float* Vs    = Kt + UNION_FLOATS;     // [128][VPAD]  Vs[s][d]
    float* Eks   = Vs + 128*VPAD;         // [9][QPAD]
    float* Evs   = Eks + NREL*QPAD;       // [9][QPAD]
    float* biasS = Evs + NREL*QPAD;       // [64][9]
    float* bandS = biasS + 64*NREL;       // [64][9]
    float* mS    = bandS + 64*NREL;       // [64]
    float* lS    = mS + 64;               // [64]
    float* aS    = lS + 64;               // [64]
    int*   maskS = (int*)(aS + 64);       // [128]

    const int b = blockIdx.z, h = blockIdx.y, t0 = blockIdx.x * 64;
    const int tid = threadIdx.x;
    const int ty = tid >> 4, tx = tid & 15;
    const int m0 = ty * 4;    // query-row base (both phases)
    const int n0 = tx * 8;    // QK: key-col base
    const int d0 = tx * 4;    // PV: d-col base
    const float rscale = 0.125f;          // 1/sqrt(64)

    // Load Q transposed (scaled), rel embeddings.
    const float* Qg = g_Q + (((size_t)b * HH + h) * TT + t0) * DD;
    for (int idx = tid; idx < 64 * 16; idx += 256) {
        int r = idx >> 4, c4 = (idx & 15) * 4;
        float4 q4 = *reinterpret_cast<const float4*>(Qg + (size_t)r * DD + c4);
        Qt[(c4 + 0) * QPAD + r] = q4.x * rscale;
        Qt[(c4 + 1) * QPAD + r] = q4.y * rscale;
        Qt[(c4 + 2) * QPAD + r] = q4.z * rscale;
        Qt[(c4 + 3) * QPAD + r] = q4.w * rscale;
    }
    for (int idx = tid; idx < NREL * 64; idx += 256) {
        int j = idx >> 6, k = idx & 63;
        Eks[j * QPAD + k] = Ek[idx];
        Evs[j * QPAD + k] = Ev[idx];
    }
    if (tid < 64) { mS[tid] = -1e30f; lS[tid] = 0.0f; }
    for (int idx = tid; idx < 64 * NREL; idx += 256) bandS[idx] = 0.0f;
    __syncthreads();

    // Band bias: biasS[r][j] = sum_k Qt[k][r] * Eks[j][k]   (Qt already /8)
    for (int idx = tid; idx < 64 * NREL; idx += 256) {
        int r = idx / NREL, j = idx % NREL;
        float s = 0.0f;
        #pragma unroll
        for (int k = 0; k < 64; k++) s += Qt[k * QPAD + r] * Eks[j * QPAD + k];
        biasS[idx] = s;
    }

    u64t oacc2[4][2] = {};   // [i][d-pair]
    const float* Kg = g_K + ((size_t)b * HH + h) * TT * DD;
    const float* Vg = g_V + ((size_t)b * HH + h) * TT * DD;
    const int*   maskb = mask + (size_t)b * TT;

    for (int s0 = 0; s0 < TT; s0 += 128) {
        __syncthreads();   // S1: prev PV done reading Pt/Vs (covers biasS on it 0)
        // Load K transposed (Kt[k][n], n = s-row) + V + mask.
        for (int idx = tid; idx < 128 * 16; idx += 256) {
            int r = idx >> 4, c4 = (idx & 15) * 4;
            float4 k4 = *reinterpret_cast<const float4*>(Kg + (size_t)(s0 + r) * DD + c4);
            Kt[(c4 + 0) * KPAD + r] = k4.x;
            Kt[(c4 + 1) * KPAD + r] = k4.y;
            Kt[(c4 + 2) * KPAD + r] = k4.z;
            Kt[(c4 + 3) * KPAD + r] = k4.w;
            float4 v4 = *reinterpret_cast<const float4*>(Vg + (size_t)(s0 + r) * DD + c4);
            *reinterpret_cast<float4*>(&Vs[r * VPAD + c4]) = v4;
        }
        if (tid < 128) maskS[tid] = maskb[s0 + tid];
        __syncthreads();   // S2: tiles ready

        // S = Q K^T : acc packed over n; K pairs natural, Q splats.
        u64t sacc2[4][4] = {};   // [i][n-pair]
        #pragma unroll 8
        for (int kk = 0; kk < 64; kk++) {
            float4 qa = *reinterpret_cast<float4*>(&Qt[kk * QPAD + m0]);
            ulonglong2 kb0 = *reinterpret_cast<ulonglong2*>(&Kt[kk * KPAD + n0]);
            ulonglong2 kb1 = *reinterpret_cast<ulonglong2*>(&Kt[kk * KPAD + n0 + 4]);
            u64t q0 = pk2(qa.x, qa.x), q1 = pk2(qa.y, qa.y);
            u64t q2 = pk2(qa.z, qa.z), q3 = pk2(qa.w, qa.w);
            fma2(sacc2[0][0], q0, kb0.x); fma2(sacc2[0][1], q0, kb0.y);
            fma2(sacc2[0][2], q0, kb1.x); fma2(sacc2[0][3], q0, kb1.y);
            fma2(sacc2[1][0], q1, kb0.x); fma2(sacc2[1][1], q1, kb0.y);
            fma2(sacc2[1][2], q1, kb1.x); fma2(sacc2[1][3], q1, kb1.y);
            fma2(sacc2[2][0], q2, kb0.x); fma2(sacc2[2][1], q2, kb0.y);
            fma2(sacc2[2][2], q2, kb1.x); fma2(sacc2[2][3], q2, kb1.y);
            fma2(sacc2[3][0], q3, kb0.x); fma2(sacc2[3][1], q3, kb0.y);
            fma2(sacc2[3][2], q3, kb1.x); fma2(sacc2[3][3], q3, kb1.y);
        }
        __syncthreads();   // S3: all Kt reads complete before Pt overwrite

        // bias + mask -> Pt[s][r] (aliases Kt)
        #pragma unroll
        for (int jp = 0; jp < 4; jp++) {
            float lo[4], hi[4];
            #pragma unroll
            for (int i = 0; i < 4; i++) upk2(sacc2[i][jp], lo[i], hi[i]);
            {
                int n = n0 + 2 * jp;
                int msk = maskS[n];
                float4 v; float* vv = reinterpret_cast<float*>(&v);
                #pragma unroll
                for (int i = 0; i < 4; i++) {
                    int r = m0 + i;
                    int delta = (s0 + n) - (t0 + r);
                    float val = lo[i];
                    if (delta >= -4 && delta <= 4) val += biasS[r * NREL + delta + 4];
                    if (msk == 0) val = -10000.0f;
                    vv[i] = val;
                }
                *reinterpret_cast<float4*>(&Pt[n * QPAD + m0]) = v;
            }
            {
                int n = n0 + 2 * jp + 1;
                int msk = maskS[n];
                float4 v; float* vv = reinterpret_cast<float*>(&v);
                #pragma unroll
                for (int i = 0; i < 4; i++) {
                    int r = m0 + i;
                    int delta = (s0 + n) - (t0 + r);
                    float val = hi[i];
                    if (delta >= -4 && delta <= 4) val += biasS[r * NREL + delta + 4];
                    if (msk == 0) val = -10000.0f;
                    vv[i] = val;
                }
                *reinterpret_cast<float4*>(&Pt[n * QPAD + m0]) = v;
            }
        }
        __syncthreads();   // S4: Pt complete

        // Online softmax: 4 threads per row, 32 cols each, shuffle reductions.
        {
            const int r = tid >> 2, q = tid & 3;
            float* colp = Pt + (q * 32) * QPAD + r;
            float mold = mS[r];
            float mloc = -1e30f;
            #pragma unroll 8
            for (int s = 0; s < 32; s++) mloc = fmaxf(mloc, colp[s * QPAD]);
            mloc = fmaxf(mloc, __shfl_xor_sync(0xffffffffu, mloc, 1));
            mloc = fmaxf(mloc, __shfl_xor_sync(0xffffffffu, mloc, 2));
            float mb = fmaxf(mold, mloc);
            float sum = 0.0f;
            #pragma unroll 8
            for (int s = 0; s < 32; s++) {
                float pv = __expf(colp[s * QPAD] - mb);
                colp[s * QPAD] = pv;
                sum += pv;
            }
            sum += __shfl_xor_sync(0xffffffffu, sum, 1);
            sum += __shfl_xor_sync(0xffffffffu, sum, 2);
            float alpha = __expf(mold - mb);
            __syncwarp();   // sibling exp writes visible for band read
            if (q == 0) {
                mS[r] = mb;
                lS[r] = lS[r] * alpha + sum;
                aS[r] = alpha;
                #pragma unroll
                for (int j = 0; j < NREL; j++) {
                    int s = t0 + r + j - 4;
                    float bvv = bandS[r * NREL + j] * alpha;
                    if (s >= s0 && s < s0 + 128) bvv = Pt[(s - s0) * QPAD + r];
                    bandS[r * NREL + j] = bvv;
                }
            }
        }
        __syncthreads();   // S5: softmax done

        // rescale + P@V : acc packed over d; V pairs natural, P splats.
        {
            #pragma unroll
            for (int i = 0; i < 4; i++) {
                float a = aS[m0 + i];
                u64t al = pk2(a, a);
                mul2(oacc2[i][0], al);
                mul2(oacc2[i][1], al);
            }
        }
        #pragma unroll 8
        for (int s = 0; s < 128; s++) {
            float4 pa = *reinterpret_cast<float4*>(&Pt[s * QPAD + m0]);
            ulonglong2 vb = *reinterpret_cast<ulonglong2*>(&Vs[s * VPAD + d0]);
            u64t p0 = pk2(pa.x, pa.x), p1 = pk2(pa.y, pa.y);
            u64t p2 = pk2(pa.z, pa.z), p3 = pk2(pa.w, pa.w);
            fma2(oacc2[0][0], p0, vb.x); fma2(oacc2[0][1], p0, vb.y);
            fma2(oacc2[1][0], p1, vb.x); fma2(oacc2[1][1], p1, vb.y);
            fma2(oacc2[2][0], p2, vb.x); fma2(oacc2[2][1], p2, vb.y);
            fma2(oacc2[3][0], p3, vb.x); fma2(oacc2[3][1], p3, vb.y);
        }
    }
    __syncthreads();

    // finalize: (PV + band@Ev)/l ; store g_O[b, h*64+d, t0+r] (contig in t)
    float oc[4][4];
    #pragma unroll
    for (int i = 0; i < 4; i++) {
        upk2(oacc2[i][0], oc[i][0], oc[i][1]);
        upk2(oacc2[i][1], oc[i][2], oc[i][3]);
    }
    float invl[4];
    #pragma unroll
    for (int i = 0; i < 4; i++) invl[i] = 1.0f / lS[m0 + i];
    float* Og = g_O + (((size_t)b * HH + h) * DD) * TT + t0;
    #pragma unroll
    for (int j = 0; j < 4; j++) {
        int dcol = d0 + j;
        float4 v4; float* vv = reinterpret_cast<float*>(&v4);
        #pragma unroll
        for (int i = 0; i < 4; i++) {
            float v = oc[i][j];
            int r = m0 + i;
            #pragma unroll
            for (int e = 0; e < NREL; e++)
                v += bandS[r * NREL + e] * Evs[e * QPAD + dcol];
            vv[i] = v * invl[i];
        }
        *reinterpret_cast<float4*>(&Og[(size_t)dcol * TT + m0]) = v4;
    }
}

// ---------------------------------------------------------------------------
extern "C" void kernel_launch(void* const* d_in, const int* in_sizes, int n_in,
                              void* d_out, int out_size)
{
    const float* x    = (const float*)d_in[0];
    const int*   mask = (const int*)d_in[1];
    const float* Wq = (const float*)d_in[2];
    const float* bq = (const float*)d_in[3];
    const float* Wk = (const float*)d_in[4];
    const float* bk = (const float*)d_in[5];
    const float* Wv = (const float*)d_in[6];
    const float* bv = (const float*)d_in[7];
    const float* Wo = (const float*)d_in[8];
    const float* bo = (const float*)d_in[9];
    const float* Ek = (const float*)d_in[10];
    const float* Ev = (const float*)d_in[11];
    float* out = (float*)d_out;

    float* Op;
    cudaGetSymbolAddress((void**)&Op, g_O);

    const size_t smem_attn = SMEM_ATTN_FLOATS * sizeof(float);
    cudaFuncSetAttribute(attn_kernel,
                         cudaFuncAttributeMaxDynamicSharedMemorySize,
                         (int)smem_attn);

    dim3 gp(TT / 64, HH, BB);
    qkv_kernel<<<gp, 256>>>(Wq, bq, Wk, bk, Wv, bv, x);

    dim3 ga(TT / 64, HH, BB);
    attn_kernel<<<ga, 256, smem_attn>>>(mask, Ek, Ev);

    dim3 go(TT / 64, CC / 64, BB);
    out_kernel<<<go, 256>>>(Wo, bo, Op, out);
}

// round 9
// speedup vs baseline: 1.2238x; 1.2238x over previous
#include <cuda_runtime.h>
#include <cuda_bf16.h>

// Fixed problem shape.
#define BB 4
#define CC 512
#define TT 1024
#define HH 8
#define DD 64
#define NREL 9
#define RPAD 132   // Qt/Pt row stride: 128 q-rows + 4 pad (16B-aligned)
#define NPAD 68    // Kt row stride: 64 s-cols + 4 pad

// Scratch (no allocations allowed) — 32 MB total.
__device__ float g_Q[BB*HH*TT*DD];   // [B,H,T,d]
__device__ float g_K[BB*HH*TT*DD];   // [B,H,T,d]
__device__ float g_V[BB*HH*TT*DD];   // [B,H,T,d]
__device__ float g_O[BB*CC*TT];      // [B,C,T] attention output (pre-Wo)

// ---- packed f32x2 helpers (sm_100+: SASS FFMA2; only reachable via PTX) ----
typedef unsigned long long u64t;

__device__ __forceinline__ u64t pk2(float lo, float hi) {
    u64t d;
    asm("mov.b64 %0, {%1, %2};"
        : "=l"(d) : "r"(__float_as_uint(lo)), "r"(__float_as_uint(hi)));
    return d;
}
__device__ __forceinline__ void upk2(u64t v, float& lo, float& hi) {
    unsigned a, b;
    asm("mov.b64 {%0, %1}, %2;" : "=r"(a), "=r"(b) : "l"(v));
    lo = __uint_as_float(a); hi = __uint_as_float(b);
}
__device__ __forceinline__ void fma2(u64t& d, u64t a, u64t b) {
    asm("fma.rn.f32x2 %0, %1, %2, %0;" : "+l"(d) : "l"(a), "l"(b));
}
__device__ __forceinline__ void mul2(u64t& d, u64t a) {
    asm("mul.rn.f32x2 %0, %0, %1;" : "+l"(d) : "l"(a));
}

// ---------------------------------------------------------------------------
// Fused QKV projection, double-buffered, FFMA2 micro-kernel (proven: 145us).
// ---------------------------------------------------------------------------
__global__ __launch_bounds__(256)
void qkv_kernel(const float* __restrict__ Wq, const float* __restrict__ bq_,
                const float* __restrict__ Wk, const float* __restrict__ bk_,
                const float* __restrict__ Wv, const float* __restrict__ bv_,
                const float* __restrict__ X)
{
    __shared__ float Ws[2][3][16][64];   // [buf][g][kk][m]
    __shared__ float Xs[2][16][64];      // [buf][kk][n]

    const int b  = blockIdx.z;
    const int h  = blockIdx.y;
    const int o0 = h * 64;
    const int t0 = blockIdx.x * 64;
    const int tid = threadIdx.x;
    const int ty = tid >> 4, tx = tid & 15;
    const int m0 = ty * 4, n0 = tx * 4;
    const int wm  = tid >> 2;
    const int wk4 = (tid & 3) * 4;
    const int xkk = tid >> 4;
    const int xnn = (tid & 15) * 4;

    const float* Xb = X + (size_t)b * CC * TT;

    u64t acc2[3][2][4] = {};

    float4 wr0 = *reinterpret_cast<const float4*>(&Wq[(size_t)(o0 + wm) * CC + wk4]);
    float4 wr1 = *reinterpret_cast<const float4*>(&Wk[(size_t)(o0 + wm) * CC + wk4]);
    float4 wr2 = *reinterpret_cast<const float4*>(&Wv[(size_t)(o0 + wm) * CC + wk4]);
    float4 xr  = *reinterpret_cast<const float4*>(&Xb[(size_t)xkk * TT + t0 + xnn]);
    Ws[0][0][wk4+0][wm] = wr0.x; Ws[0][0][wk4+1][wm] = wr0.y;
    Ws[0][0][wk4+2][wm] = wr0.z; Ws[0][0][wk4+3][wm] = wr0.w;
    Ws[0][1][wk4+0][wm] = wr1.x; Ws[0][1][wk4+1][wm] = wr1.y;
    Ws[0][1][wk4+2][wm] = wr1.z; Ws[0][1][wk4+3][wm] = wr1.w;
    Ws[0][2][wk4+0][wm] = wr2.x; Ws[0][2][wk4+1][wm] = wr2.y;
    Ws[0][2][wk4+2][wm] = wr2.z; Ws[0][2][wk4+3][wm] = wr2.w;
    *reinterpret_cast<float4*>(&Xs[0][xkk][xnn]) = xr;
    __syncthreads();

    int p = 0;
    for (int it = 0; it < CC / 16; it++) {
        const int c1 = (it + 1) * 16;
        if (it < CC / 16 - 1) {
            wr0 = *reinterpret_cast<const float4*>(&Wq[(size_t)(o0 + wm) * CC + c1 + wk4]);
            wr1 = *reinterpret_cast<const float4*>(&Wk[(size_t)(o0 + wm) * CC + c1 + wk4]);
            wr2 = *reinterpret_cast<const float4*>(&Wv[(size_t)(o0 + wm) * CC + c1 + wk4]);
            xr  = *reinterpret_cast<const float4*>(&Xb[(size_t)(c1 + xkk) * TT + t0 + xnn]);
        }
        #pragma unroll
        for (int kk = 0; kk < 16; kk++) {
            float4 xb = *reinterpret_cast<float4*>(&Xs[p][kk][n0]);
            u64t bd[4];
            bd[0] = pk2(xb.x, xb.x); bd[1] = pk2(xb.y, xb.y);
            bd[2] = pk2(xb.z, xb.z); bd[3] = pk2(xb.w, xb.w);
            #pragma unroll
            for (int g = 0; g < 3; g++) {
                float4 wa = *reinterpret_cast<float4*>(&Ws[p][g][kk][m0]);
                u64t a01 = pk2(wa.x, wa.y);
                u64t a23 = pk2(wa.z, wa.w);
                #pragma unroll
                for (int j = 0; j < 4; j++) {
                    fma2(acc2[g][0][j], a01, bd[j]);
                    fma2(acc2[g][1][j], a23, bd[j]);
                }
            }
        }
        if (it < CC / 16 - 1) {
            const int np = p ^ 1;
            Ws[np][0][wk4+0][wm] = wr0.x; Ws[np][0][wk4+1][wm] = wr0.y;
            Ws[np][0][wk4+2][wm] = wr0.z; Ws[np][0][wk4+3][wm] = wr0.w;
            Ws[np][1][wk4+0][wm] = wr1.x; Ws[np][1][wk4+1][wm] = wr1.y;
            Ws[np][1][wk4+2][wm] = wr1.z; Ws[np][1][wk4+3][wm] = wr1.w;
            Ws[np][2][wk4+0][wm] = wr2.x; Ws[np][2][wk4+1][wm] = wr2.y;
            Ws[np][2][wk4+2][wm] = wr2.z; Ws[np][2][wk4+3][wm] = wr2.w;
            *reinterpret_cast<float4*>(&Xs[np][xkk][xnn]) = xr;
        }
        __syncthreads();
        p ^= 1;
    }

    #pragma unroll
    for (int g = 0; g < 3; g++) {
        const float* bias = (g == 0) ? bq_ : (g == 1) ? bk_ : bv_;
        float bb0 = bias[o0 + m0 + 0];
        float bb1 = bias[o0 + m0 + 1];
        float bb2 = bias[o0 + m0 + 2];
        float bb3 = bias[o0 + m0 + 3];
        float* Yb = ((g == 0) ? g_Q : (g == 1) ? g_K : g_V)
                    + (((size_t)b * HH + h) * TT + t0) * DD;
        #pragma unroll
        for (int j = 0; j < 4; j++) {
            float f0, f1, f2, f3;
            upk2(acc2[g][0][j], f0, f1);
            upk2(acc2[g][1][j], f2, f3);
            float4 v;
            v.x = f0 + bb0; v.y = f1 + bb1; v.z = f2 + bb2; v.w = f3 + bb3;
            *reinterpret_cast<float4*>(&Yb[(size_t)(n0 + j) * DD + m0]) = v;
        }
    }
}

// ---------------------------------------------------------------------------
// Output projection (proven), double-buffered FFMA2.
// ---------------------------------------------------------------------------
__global__ __launch_bounds__(256)
void out_kernel(const float* __restrict__ W, const float* __restrict__ bias,
                const float* __restrict__ X, float* __restrict__ Y)
{
    __shared__ float Ws[2][16][64];
    __shared__ float Xs[2][16][64];

    const int b  = blockIdx.z;
    const int o0 = blockIdx.y * 64;
    const int t0 = blockIdx.x * 64;
    const int tid = threadIdx.x;
    const int ty = tid >> 4, tx = tid & 15;
    const int m0 = ty * 4, n0 = tx * 4;
    const int wm  = tid >> 2;
    const int wk4 = (tid & 3) * 4;
    const int xkk = tid >> 4;
    const int xnn = (tid & 15) * 4;

    const float* Xb = X + (size_t)b * CC * TT;

    u64t acc2[2][4] = {};

    float4 wr = *reinterpret_cast<const float4*>(&W[(size_t)(o0 + wm) * CC + wk4]);
    float4 xr = *reinterpret_cast<const float4*>(&Xb[(size_t)xkk * TT + t0 + xnn]);
    Ws[0][wk4+0][wm] = wr.x; Ws[0][wk4+1][wm] = wr.y;
    Ws[0][wk4+2][wm] = wr.z; Ws[0][wk4+3][wm] = wr.w;
    *reinterpret_cast<float4*>(&Xs[0][xkk][xnn]) = xr;
    __syncthreads();

    int p = 0;
    for (int it = 0; it < CC / 16; it++) {
        const int c1 = (it + 1) * 16;
        if (it < CC / 16 - 1) {
            wr = *reinterpret_cast<const float4*>(&W[(size_t)(o0 + wm) * CC + c1 + wk4]);
            xr = *reinterpret_cast<const float4*>(&Xb[(size_t)(c1 + xkk) * TT + t0 + xnn]);
        }
        #pragma unroll
        for (int kk = 0; kk < 16; kk++) {
            float4 xb = *reinterpret_cast<float4*>(&Xs[p][kk][n0]);
            float4 wa = *reinterpret_cast<float4*>(&Ws[p][kk][m0]);
            u64t a01 = pk2(wa.x, wa.y);
            u64t a23 = pk2(wa.z, wa.w);
            u64t bd[4];
            bd[0] = pk2(xb.x, xb.x); bd[1] = pk2(xb.y, xb.y);
            bd[2] = pk2(xb.z, xb.z); bd[3] = pk2(xb.w, xb.w);
            #pragma unroll
            for (int j = 0; j < 4; j++) {
                fma2(acc2[0][j], a01, bd[j]);
                fma2(acc2[1][j], a23, bd[j]);
            }
        }
        if (it < CC / 16 - 1) {
            const int np = p ^ 1;
            Ws[np][wk4+0][wm] = wr.x; Ws[np][wk4+1][wm] = wr.y;
            Ws[np][wk4+2][wm] = wr.z; Ws[np][wk4+3][wm] = wr.w;
            *reinterpret_cast<float4*>(&Xs[np][xkk][xnn]) = xr;
        }
        __syncthreads();
        p ^= 1;
    }

    float accv[4][4];
    #pragma unroll
    for (int j = 0; j < 4; j++) {
        upk2(acc2[0][j], accv[0][j], accv[1][j]);
        upk2(acc2[1][j], accv[2][j], accv[3][j]);
    }
    #pragma unroll
    for (int i = 0; i < 4; i++) {
        float bv = bias[o0 + m0 + i];
        float4 v;
        v.x = accv[i][0] + bv; v.y = accv[i][1] + bv;
        v.z = accv[i][2] + bv; v.w = accv[i][3] + bv;
        *reinterpret_cast<float4*>(
            &Y[((size_t)b * CC + o0 + m0 + i) * TT + t0 + n0]) = v;
    }
}

// ---------------------------------------------------------------------------
// Flash attention: 128 q-rows per block, 64-wide s-tiles, 512 threads.
// Per-thread micro-kernel identical to the proven 546.9us version
// (4x4 tiles, sacc2[2][4]+oacc2[2][4] accumulators => no reg-cap spills).
//   score[t,s] = (q.k)/8 + [|s-t|<=4](q.Ek[s-t+4])/8 ; mask==0 -> -10000
//   out[t]     = softmax(score) @ V + sum_e p[t, t+e-4] * Ev[e]
// ---------------------------------------------------------------------------
#define SMEM_ATTN_FLOATS (64*RPAD /*Qt*/ + 64*NPAD /*Kt*/ + 64*64 /*Vs*/ \
                          + 64*RPAD /*Pt*/ + NREL*NPAD /*Eks*/ + NREL*NPAD /*Evs*/ \
                          + 128*NREL /*biasS*/ + 128*NREL /*bandS*/ \
                          + 128*3 /*m,l,a*/ + 64 /*mask*/)

__global__ __launch_bounds__(512)
void attn_kernel(const int* __restrict__ mask,
                 const float* __restrict__ Ek, const float* __restrict__ Ev)
{
    extern __shared__ float sm[];
    float* Qt    = sm;                   // [64][RPAD]  Qt[k][r], pre-scaled by 1/8
    float* Kt    = Qt   + 64*RPAD;       // [64][NPAD]  Kt[k][n]
    float* Vs    = Kt   + 64*NPAD;       // [64][64]    Vs[s][d]
    float* Pt    = Vs   + 64*64;         // [64][RPAD]  Pt[s][r]
    float* Eks   = Pt   + 64*RPAD;       // [9][NPAD]
    float* Evs   = Eks  + NREL*NPAD;     // [9][NPAD]
    float* biasS = Evs  + NREL*NPAD;     // [128][9]
    float* bandS = biasS + 128*NREL;     // [128][9]
    float* mS    = bandS + 128*NREL;     // [128]
    float* lS    = mS + 128;             // [128]
    float* aS    = lS + 128;             // [128]
    int*   maskS = (int*)(aS + 128);     // [64]

    const int b = blockIdx.z, h = blockIdx.y, t0 = blockIdx.x * 128;
    const int tid = threadIdx.x;
    const int ty = tid >> 4, tx = tid & 15;   // ty 0..31, tx 0..15
    const int m0 = ty * 4;    // q-row base (0..124)
    const int n0 = tx * 4;    // s-col base / d-col base
    const float rscale = 0.125f;          // 1/sqrt(64)

    // Load Q transposed (scaled): 128 rows x 16 float4 cols.
    const float* Qg = g_Q + (((size_t)b * HH + h) * TT + t0) * DD;
    for (int idx = tid; idx < 128 * 16; idx += 512) {
        int r = idx >> 4, c4 = (idx & 15) * 4;
        float4 q4 = *reinterpret_cast<const float4*>(Qg + (size_t)r * DD + c4);
        Qt[(c4 + 0) * RPAD + r] = q4.x * rscale;
        Qt[(c4 + 1) * RPAD + r] = q4.y * rscale;
        Qt[(c4 + 2) * RPAD + r] = q4.z * rscale;
        Qt[(c4 + 3) * RPAD + r] = q4.w * rscale;
    }
    for (int idx = tid; idx < NREL * 64; idx += 512) {
        int j = idx >> 6, k = idx & 63;
        Eks[j * NPAD + k] = Ek[idx];
        Evs[j * NPAD + k] = Ev[idx];
    }
    if (tid < 128) { mS[tid] = -1e30f; lS[tid] = 0.0f; }
    for (int idx = tid; idx < 128 * NREL; idx += 512) bandS[idx] = 0.0f;
    __syncthreads();

    // Band bias: biasS[r][j] = sum_k Qt[k][r] * Eks[j][k]   (Qt already /8)
    for (int idx = tid; idx < 128 * NREL; idx += 512) {
        int r = idx / NREL, j = idx % NREL;
        float s = 0.0f;
        #pragma unroll
        for (int k = 0; k < 64; k++) s += Qt[k * RPAD + r] * Eks[j * NPAD + k];
        biasS[idx] = s;
    }

    u64t oacc2[2][4] = {};   // [r-pair][j]
    const float* Kg = g_K + ((size_t)b * HH + h) * TT * DD;
    const float* Vg = g_V + ((size_t)b * HH + h) * TT * DD;
    const int*   maskb = mask + (size_t)b * TT;

    for (int s0 = 0; s0 < TT; s0 += 64) {
        __syncthreads();   // S1: prev PV done reading Pt/Vs (covers biasS on it 0)
        for (int idx = tid; idx < 64 * 16; idx += 512) {
            int r = idx >> 4, c4 = (idx & 15) * 4;
            float4 k4 = *reinterpret_cast<const float4*>(Kg + (size_t)(s0 + r) * DD + c4);
            Kt[(c4 + 0) * NPAD + r] = k4.x;
            Kt[(c4 + 1) * NPAD + r] = k4.y;
            Kt[(c4 + 2) * NPAD + r] = k4.z;
            Kt[(c4 + 3) * NPAD + r] = k4.w;
            float4 v4 = *reinterpret_cast<const float4*>(Vg + (size_t)(s0 + r) * DD + c4);
            *reinterpret_cast<float4*>(Vs + r * 64 + c4) = v4;
        }
        if (tid < 64) maskS[tid] = maskb[s0 + tid];
        __syncthreads();   // S2: tiles ready

        // S = Q K^T : both operands LDS.128, FFMA2 packed over r (proven form).
        u64t sacc2[2][4] = {};
        #pragma unroll 16
        for (int kk = 0; kk < 64; kk++) {
            float4 qa = *reinterpret_cast<float4*>(&Qt[kk * RPAD + m0]);
            float4 kb = *reinterpret_cast<float4*>(&Kt[kk * NPAD + n0]);
            u64t q01 = pk2(qa.x, qa.y);
            u64t q23 = pk2(qa.z, qa.w);
            u64t kd[4];
            kd[0] = pk2(kb.x, kb.x); kd[1] = pk2(kb.y, kb.y);
            kd[2] = pk2(kb.z, kb.z); kd[3] = pk2(kb.w, kb.w);
            #pragma unroll
            for (int j = 0; j < 4; j++) {
                fma2(sacc2[0][j], q01, kd[j]);
                fma2(sacc2[1][j], q23, kd[j]);
            }
        }
        float sacc[4][4];
        #pragma unroll
        for (int j = 0; j < 4; j++) {
            upk2(sacc2[0][j], sacc[0][j], sacc[1][j]);
            upk2(sacc2[1][j], sacc[2][j], sacc[3][j]);
        }
        // bias + mask -> Pt (transposed, vectorized over r)
        #pragma unroll
        for (int j = 0; j < 4; j++) {
            int n = n0 + j;
            int msk = maskS[n];
            float4 v;
            float* vv = reinterpret_cast<float*>(&v);
            #pragma unroll
            for (int i = 0; i < 4; i++) {
                int r = m0 + i;
                int delta = (s0 + n) - (t0 + r);
                float val = sacc[i][j];
                if (delta >= -4 && delta <= 4) val += biasS[r * NREL + delta + 4];
                if (msk == 0) val = -10000.0f;
                vv[i] = val;
            }
            *reinterpret_cast<float4*>(&Pt[n * RPAD + m0]) = v;
        }
        __syncthreads();   // S3: Pt complete

        // Online softmax: 4 threads per row (128 rows x 4 = 512), 16 cols each.
        {
            const int r = tid >> 2, q = tid & 3;
            float* colp = Pt + (q * 16) * RPAD + r;
            float mold = mS[r];
            float mloc = -1e30f;
            #pragma unroll
            for (int s = 0; s < 16; s++) mloc = fmaxf(mloc, colp[s * RPAD]);
            mloc = fmaxf(mloc, __shfl_xor_sync(0xffffffffu, mloc, 1));
            mloc = fmaxf(mloc, __shfl_xor_sync(0xffffffffu, mloc, 2));
            float mb = fmaxf(mold, mloc);
            float sum = 0.0f;
            #pragma unroll
            for (int s = 0; s < 16; s++) {
                float pv = __expf(colp[s * RPAD] - mb);
                colp[s * RPAD] = pv;
                sum += pv;
            }
            sum += __shfl_xor_sync(0xffffffffu, sum, 1);
            sum += __shfl_xor_sync(0xffffffffu, sum, 2);
            float alpha = __expf(mold - mb);
            __syncwarp();   // sibling exp writes visible for band read
            if (q == 0) {
                mS[r] = mb;
                lS[r] = lS[r] * alpha + sum;
                aS[r] = alpha;
                #pragma unroll
                for (int j = 0; j < NREL; j++) {
                    int s = t0 + r + j - 4;
                    float bvv = bandS[r * NREL + j] * alpha;
                    if (s >= s0 && s < s0 + 64) bvv = Pt[(s - s0) * RPAD + r];
                    bandS[r * NREL + j] = bvv;
                }
            }
        }
        __syncthreads();   // S4: softmax done

        // rescale + P@V : proven form (acc packed over r, V splats).
        {
            u64t a01 = pk2(aS[m0 + 0], aS[m0 + 1]);
            u64t a23 = pk2(aS[m0 + 2], aS[m0 + 3]);
            #pragma unroll
            for (int j = 0; j < 4; j++) {
                mul2(oacc2[0][j], a01);
                mul2(oacc2[1][j], a23);
            }
        }
        #pragma unroll 8
        for (int s = 0; s < 64; s++) {
            float4 pa = *reinterpret_cast<float4*>(&Pt[s * RPAD + m0]);
            float4 vb = *reinterpret_cast<float4*>(&Vs[s * 64 + n0]);
            u64t p01 = pk2(pa.x, pa.y);
            u64t p23 = pk2(pa.z, pa.w);
            u64t vd[4];
            vd[0] = pk2(vb.x, vb.x); vd[1] = pk2(vb.y, vb.y);
            vd[2] = pk2(vb.z, vb.z); vd[3] = pk2(vb.w, vb.w);
            #pragma unroll
            for (int j = 0; j < 4; j++) {
                fma2(oacc2[0][j], p01, vd[j]);
                fma2(oacc2[1][j], p23, vd[j]);
            }
        }
    }
    __syncthreads();

    // finalize: (PV + band@Ev)/l ; store g_O[b, h*64+d, t0+r] (contig in t)
    float oacc[4][4];
    #pragma unroll
    for (int j = 0; j < 4; j++) {
        upk2(oacc2[0][j], oacc[0][j], oacc[1][j]);
        upk2(oacc2[1][j], oacc[2][j], oacc[3][j]);
    }
    float invl[4];
    #pragma unroll
    for (int i = 0; i < 4; i++) invl[i] = 1.0f / lS[m0 + i];
    float* Og = g_O + (((size_t)b * HH + h) * DD) * TT + t0;
    #pragma unroll
    for (int j = 0; j < 4; j++) {
        int dcol = n0 + j;
        float4 v4; float* vv = reinterpret_cast<float*>(&v4);
        #pragma unroll
        for (int i = 0; i < 4; i++) {
            float v = oacc[i][j];
            int r = m0 + i;
            #pragma unroll
            for (int e = 0; e < NREL; e++)
                v += bandS[r * NREL + e] * Evs[e * NPAD + dcol];
            vv[i] = v * invl[i];
        }
        *reinterpret_cast<float4*>(&Og[(size_t)dcol * TT + m0]) = v4;
    }
}

// ---------------------------------------------------------------------------
extern "C" void kernel_launch(void* const* d_in, const int* in_sizes, int n_in,
                              void* d_out, int out_size)
{
    const float* x    = (const float*)d_in[0];
    const int*   mask = (const int*)d_in[1];
    const float* Wq = (const float*)d_in[2];
    const float* bq = (const float*)d_in[3];
    const float* Wk = (const float*)d_in[4];
    const float* bk = (const float*)d_in[5];
    const float* Wv = (const float*)d_in[6];
    const float* bv = (const float*)d_in[7];
    const float* Wo = (const float*)d_in[8];
    const float* bo = (const float*)d_in[9];
    const float* Ek = (const float*)d_in[10];
    const float* Ev = (const float*)d_in[11];
    float* out = (float*)d_out;

    float* Op;
    cudaGetSymbolAddress((void**)&Op, g_O);

    const size_t smem_attn = SMEM_ATTN_FLOATS * sizeof(float);
    cudaFuncSetAttribute(attn_kernel,
                         cudaFuncAttributeMaxDynamicSharedMemorySize,
                         (int)smem_attn);

    dim3 gp(TT / 64, HH, BB);
    qkv_kernel<<<gp, 256>>>(Wq, bq, Wk, bk, Wv, bv, x);

    dim3 ga(TT / 128, HH, BB);
    attn_kernel<<<ga, 512, smem_attn>>>(mask, Ek, Ev);

    dim3 go(TT / 64, CC / 64, BB);
    out_kernel<<<go, 256>>>(Wo, bo, Op, out);
}